// round 6
// baseline (speedup 1.0000x reference)
#include <cuda_runtime.h>
#include <cstdint>
#include <math.h>

// ---------------- problem constants ----------------
#define BT   16384          // B*T
#define D    1024
#define DQ   256
#define DH   512
#define NP   6              // digit positions
#define NCAT 4096           // sign(512) + 6*512 + aux(512)
#define KDIM 1024

// ---------------- scratch (device globals; no allocation allowed) ----------
__device__ float g_ctx [(size_t)BT * D];        // 64 MB : raw ctx -> context (in place)
__device__ float g_H   [(size_t)BT * NCAT];     // 256 MB : head pre-activations
__device__ float g_Wcat[(size_t)KDIM * NCAT];   // 16 MB : concatenated head W1
__device__ float g_opc [9  * D];                // op contribution to ctx pre-LN
__device__ float g_ptc [10 * D];                // pt contribution (+ctx_b)
__device__ float g_hbias[NCAT];                 // per-column bias for H

// ---------------- helpers ----------------
__device__ __forceinline__ uint32_t f2tf32(float x) {
    uint32_t r;
    asm("cvt.rna.tf32.f32 %0, %1;" : "=r"(r) : "f"(x));
    return r;
}

__device__ __forceinline__ void mma_tf32(float* d, const uint32_t* a, uint32_t b0, uint32_t b1) {
    asm volatile(
        "mma.sync.aligned.m16n8k8.row.col.f32.tf32.tf32.f32 "
        "{%0,%1,%2,%3},{%4,%5,%6,%7},{%8,%9},{%0,%1,%2,%3};"
        : "+f"(d[0]), "+f"(d[1]), "+f"(d[2]), "+f"(d[3])
        : "r"(a[0]), "r"(a[1]), "r"(a[2]), "r"(a[3]), "r"(b0), "r"(b1));
}

__device__ __forceinline__ float gelu_exact(float x) {
    return 0.5f * x * (1.0f + erff(x * 0.70710678118654752440f));
}

__device__ __forceinline__ float warp_allreduce(float v) {
#pragma unroll
    for (int o = 16; o; o >>= 1) v += __shfl_xor_sync(0xffffffffu, v, o);
    return v;
}

// ---------------- precompute: concatenated W1 [K=1024, N=4096] -------------
__global__ void pre_wcat(const float* __restrict__ sign_w1,
                         const float* __restrict__ dig_w1,
                         const float* __restrict__ aux_w1) {
    int idx = blockIdx.x * blockDim.x + threadIdx.x;       // 0 .. 1024*4096-1
    int k = idx >> 12;
    int n = idx & 4095;
    float v;
    if (n < 512) {
        v = sign_w1[k * 512 + n];
    } else if (n < 3584) {
        int p = (n - 512) >> 9;
        int h = (n - 512) & 511;
        v = dig_w1[((size_t)p * 1280 + k) * 512 + h];
    } else {
        v = aux_w1[k * 512 + (n - 3584)];
    }
    g_Wcat[(size_t)k * NCAT + n] = v;
}

// ---------------- precompute: small contribution tables --------------------
__global__ void pre_small(const float* __restrict__ op_embed,
                          const float* __restrict__ pt_embed,
                          const float* __restrict__ pos_embed,
                          const float* __restrict__ ctx_w,
                          const float* __restrict__ ctx_b,
                          const float* __restrict__ sign_b1,
                          const float* __restrict__ dig_w1,
                          const float* __restrict__ dig_b1,
                          const float* __restrict__ aux_b1) {
    int idx = blockIdx.x * blockDim.x + threadIdx.x;
    if (idx < 9 * D) {                         // op contributions
        int o = idx >> 10, j = idx & 1023;
        float s = 0.f;
        for (int q = 0; q < DQ; q++)
            s += op_embed[o * DQ + q] * ctx_w[(size_t)(1024 + q) * D + j];
        g_opc[idx] = s;
    } else if (idx < 9 * D + 10 * D) {         // pt contributions (+ctx_b)
        int i2 = idx - 9 * D;
        int pt = i2 >> 10, j = i2 & 1023;
        float s = ctx_b[j];
        for (int q = 0; q < DQ; q++)
            s += pt_embed[pt * DQ + q] * ctx_w[(size_t)(1280 + q) * D + j];
        g_ptc[i2] = s;
    } else if (idx < 9 * D + 10 * D + NCAT) {  // head bias
        int n = idx - 19 * D;
        float v;
        if (n < 512) {
            v = sign_b1[n];
        } else if (n < 3584) {
            int p = (n - 512) >> 9;
            int h = (n - 512) & 511;
            float s = dig_b1[p * 512 + h];
            for (int q = 0; q < DQ; q++)
                s += pos_embed[p * DQ + q] * dig_w1[((size_t)p * 1280 + 1024 + q) * 512 + h];
            v = s;
        } else {
            v = aux_b1[n - 3584];
        }
        g_hbias[n] = v;
    }
}

// ---------------- TF32 GEMM: C[M=16384, N] = A[16384,1024] @ B[1024,N] -----
// block tile 128x128, K-step 32, 8 warps (4M x 2N), warp tile 32x64
__global__ __launch_bounds__(256, 2)
void gemm_tf32(const float* __restrict__ A, const float* __restrict__ B,
               float* __restrict__ C, int N) {
    __shared__ uint32_t As[128][36];   // padded: stride 36 words (16B aligned, no conflicts)
    __shared__ uint32_t Bs[32][136];   // padded: stride 136 words

    const int tid  = threadIdx.x;
    const int warp = tid >> 5, lane = tid & 31;
    const int wm = warp & 3, wn = warp >> 2;
    const int g = lane >> 2, tg = lane & 3;
    const int mBase = blockIdx.y * 128;
    const int nBase = blockIdx.x * 128;

    float acc[2][8][4];
#pragma unroll
    for (int mi = 0; mi < 2; mi++)
#pragma unroll
        for (int ni = 0; ni < 8; ni++)
#pragma unroll
            for (int c = 0; c < 4; c++) acc[mi][ni][c] = 0.f;

    for (int kt = 0; kt < KDIM; kt += 32) {
        // load A tile (128 x 32), vectorized
#pragma unroll
        for (int j = 0; j < 4; j++) {
            int idx = tid + 256 * j;
            int r = idx >> 3, c = (idx & 7) << 2;
            float4 v = *(const float4*)(A + (size_t)(mBase + r) * KDIM + kt + c);
            uint4 u;
            u.x = f2tf32(v.x); u.y = f2tf32(v.y); u.z = f2tf32(v.z); u.w = f2tf32(v.w);
            *(uint4*)&As[r][c] = u;
        }
        // load B tile (32 x 128)
#pragma unroll
        for (int j = 0; j < 4; j++) {
            int idx = tid + 256 * j;
            int r = idx >> 5, c = (idx & 31) << 2;
            float4 v = *(const float4*)(B + (size_t)(kt + r) * N + nBase + c);
            uint4 u;
            u.x = f2tf32(v.x); u.y = f2tf32(v.y); u.z = f2tf32(v.z); u.w = f2tf32(v.w);
            *(uint4*)&Bs[r][c] = u;
        }
        __syncthreads();

#pragma unroll
        for (int k8 = 0; k8 < 4; k8++) {
            const int kk = k8 * 8;
            uint32_t a[2][4];
#pragma unroll
            for (int mi = 0; mi < 2; mi++) {
                int r0 = wm * 32 + mi * 16;
                a[mi][0] = As[r0 + g    ][kk + tg    ];
                a[mi][1] = As[r0 + g + 8][kk + tg    ];
                a[mi][2] = As[r0 + g    ][kk + tg + 4];
                a[mi][3] = As[r0 + g + 8][kk + tg + 4];
            }
#pragma unroll
            for (int ni = 0; ni < 8; ni++) {
                int cB = wn * 64 + ni * 8 + g;
                uint32_t b0 = Bs[kk + tg    ][cB];
                uint32_t b1 = Bs[kk + tg + 4][cB];
#pragma unroll
                for (int mi = 0; mi < 2; mi++) mma_tf32(acc[mi][ni], a[mi], b0, b1);
            }
        }
        __syncthreads();
    }

    // store
#pragma unroll
    for (int mi = 0; mi < 2; mi++) {
#pragma unroll
        for (int ni = 0; ni < 8; ni++) {
            int r0 = mBase + wm * 32 + mi * 16 + g;
            int c0 = nBase + wn * 64 + ni * 8 + tg * 2;
            *(float2*)(C + (size_t)r0 * N + c0)       = make_float2(acc[mi][ni][0], acc[mi][ni][1]);
            *(float2*)(C + (size_t)(r0 + 8) * N + c0) = make_float2(acc[mi][ni][2], acc[mi][ni][3]);
        }
    }
}

// ---------------- context: add contribs, LayerNorm(1024), GELU (in place) --
__global__ __launch_bounds__(256)
void ln_ctx(const int* __restrict__ op_type, const int* __restrict__ pt_type,
            const float* __restrict__ gam, const float* __restrict__ bet) {
    __shared__ float sred[8];
    const int t = blockIdx.x;
    const int b = t >> 11;
    const int op = op_type[b];
    const int pt = pt_type[t];
    const int tid = threadIdx.x;
    const int warp = tid >> 5, lane = tid & 31;

    float x[4];
#pragma unroll
    for (int i = 0; i < 4; i++) {
        int c = tid + 256 * i;
        x[i] = g_ctx[(size_t)t * D + c] + g_opc[op * D + c] + g_ptc[pt * D + c];
    }
    // mean
    float s = x[0] + x[1] + x[2] + x[3];
    s = warp_allreduce(s);
    if (lane == 0) sred[warp] = s;
    __syncthreads();
    float m = 0.f;
    {
        float v = (lane < 8) ? sred[lane] : 0.f;
        v = warp_allreduce(v);
        m = __shfl_sync(0xffffffffu, v, 0) * (1.0f / 1024.0f);
    }
    __syncthreads();
    // var (two-pass, matches reference)
    float q = 0.f;
#pragma unroll
    for (int i = 0; i < 4; i++) { float d = x[i] - m; q += d * d; }
    q = warp_allreduce(q);
    if (lane == 0) sred[warp] = q;
    __syncthreads();
    float var;
    {
        float v = (lane < 8) ? sred[lane] : 0.f;
        v = warp_allreduce(v);
        var = __shfl_sync(0xffffffffu, v, 0) * (1.0f / 1024.0f);
    }
    float r = rsqrtf(var + 1e-5f);
#pragma unroll
    for (int i = 0; i < 4; i++) {
        int c = tid + 256 * i;
        float y = (x[i] - m) * r * gam[c] + bet[c];
        g_ctx[(size_t)t * D + c] = gelu_exact(y);
    }
}

// ---------------- head epilogue: 1 block/token, 1 warp/segment -------------
__global__ __launch_bounds__(256)
void heads_epilogue(const float* __restrict__ sign_g,  const float* __restrict__ sign_beta,
                    const float* __restrict__ sign_w2, const float* __restrict__ sign_b2,
                    const float* __restrict__ dig_g,   const float* __restrict__ dig_beta,
                    const float* __restrict__ dig_w2,  const float* __restrict__ dig_b2,
                    const float* __restrict__ aux_w2,  const float* __restrict__ aux_b2,
                    float* __restrict__ out) {
    const int t = blockIdx.x;
    const int warp = threadIdx.x >> 5, lane = threadIdx.x & 31;
    const int segBase = warp * 512;

    float x[16];
#pragma unroll
    for (int i = 0; i < 16; i++) {
        int h = lane + 32 * i;
        x[i] = g_H[(size_t)t * NCAT + segBase + h] + g_hbias[segBase + h];
    }

    float y[16];
    if (warp < 7) {
        // LayerNorm(512) within warp
        float s = 0.f;
#pragma unroll
        for (int i = 0; i < 16; i++) s += x[i];
        s = warp_allreduce(s);
        float m = s * (1.0f / 512.0f);
        float q = 0.f;
#pragma unroll
        for (int i = 0; i < 16; i++) { float d = x[i] - m; q += d * d; }
        q = warp_allreduce(q);
        float r = rsqrtf(q * (1.0f / 512.0f) + 1e-5f);

        const float* gam;
        const float* bet;
        if (warp == 0) { gam = sign_g; bet = sign_beta; }
        else           { gam = dig_g + (warp - 1) * 512; bet = dig_beta + (warp - 1) * 512; }
#pragma unroll
        for (int i = 0; i < 16; i++) {
            int h = lane + 32 * i;
            y[i] = gelu_exact((x[i] - m) * r * gam[h] + bet[h]);
        }
    } else {
        // aux head: no LN
#pragma unroll
        for (int i = 0; i < 16; i++) y[i] = gelu_exact(x[i]);
    }

    // small matvec per segment
    const size_t S0 = (size_t)BT * 3;
    const size_t S1 = S0 + (size_t)BT * 60;
    int nout; const float* w2; const float* b2; float* obase;
    if (warp == 0)      { nout = 3;  w2 = sign_w2;                   b2 = sign_b2;             obase = out + (size_t)t * 3; }
    else if (warp < 7)  { int p = warp - 1;
                          nout = 10; w2 = dig_w2 + (size_t)p * 5120; b2 = dig_b2 + p * 10;     obase = out + S0 + (size_t)t * 60 + p * 10; }
    else                { nout = 1;  w2 = aux_w2;                    b2 = aux_b2;              obase = out + S1 + t; }

    for (int o = 0; o < nout; o++) {
        float p = 0.f;
#pragma unroll
        for (int i = 0; i < 16; i++) p += y[i] * w2[(lane + 32 * i) * nout + o];
        p = warp_allreduce(p);
        if (lane == 0) obase[o] = p + b2[o];
    }
}

// ---------------- launch ----------------
extern "C" void kernel_launch(void* const* d_in, const int* in_sizes, int n_in,
                              void* d_out, int out_size) {
    const float* hidden    = (const float*)d_in[0];
    const int*   op_type   = (const int*)  d_in[1];
    const int*   pt_type   = (const int*)  d_in[2];
    const float* op_embed  = (const float*)d_in[3];
    const float* pt_embed  = (const float*)d_in[4];
    const float* pos_embed = (const float*)d_in[5];
    const float* ctx_w     = (const float*)d_in[6];
    const float* ctx_b     = (const float*)d_in[7];
    const float* ctx_g     = (const float*)d_in[8];
    const float* ctx_beta  = (const float*)d_in[9];
    const float* sign_w1   = (const float*)d_in[10];
    const float* sign_b1   = (const float*)d_in[11];
    const float* sign_g    = (const float*)d_in[12];
    const float* sign_beta = (const float*)d_in[13];
    const float* sign_w2   = (const float*)d_in[14];
    const float* sign_b2   = (const float*)d_in[15];
    const float* dig_w1    = (const float*)d_in[16];
    const float* dig_b1    = (const float*)d_in[17];
    const float* dig_g     = (const float*)d_in[18];
    const float* dig_beta  = (const float*)d_in[19];
    const float* dig_w2    = (const float*)d_in[20];
    const float* dig_b2    = (const float*)d_in[21];
    const float* aux_w1    = (const float*)d_in[22];
    const float* aux_b1    = (const float*)d_in[23];
    const float* aux_w2    = (const float*)d_in[24];
    const float* aux_b2    = (const float*)d_in[25];
    float* out = (float*)d_out;

    float* ctx_ptr;  cudaGetSymbolAddress((void**)&ctx_ptr,  g_ctx);
    float* H_ptr;    cudaGetSymbolAddress((void**)&H_ptr,    g_H);
    float* Wcat_ptr; cudaGetSymbolAddress((void**)&Wcat_ptr, g_Wcat);

    // 1. precompute
    pre_wcat <<< (KDIM * NCAT) / 256, 256 >>> (sign_w1, dig_w1, aux_w1);
    pre_small<<< (9 * D + 10 * D + NCAT + 255) / 256, 256 >>>
        (op_embed, pt_embed, pos_embed, ctx_w, ctx_b, sign_b1, dig_w1, dig_b1, aux_b1);

    // 2. context GEMM  [16384,1024] @ [1024,1024]
    gemm_tf32<<< dim3(D / 128, BT / 128), 256 >>>(hidden, ctx_w, ctx_ptr, D);

    // 3. context LN + GELU (+ op/pt contributions), in place
    ln_ctx<<< BT, 256 >>>(op_type, pt_type, ctx_g, ctx_beta);

    // 4. fused head GEMM  [16384,1024] @ [1024,4096]
    gemm_tf32<<< dim3(NCAT / 128, BT / 128), 256 >>>(ctx_ptr, Wcat_ptr, H_ptr, NCAT);

    // 5. head epilogue -> outputs (sign | digit | aux)
    heads_epilogue<<< BT, 256 >>>(sign_g, sign_beta, sign_w2, sign_b2,
                                  dig_g, dig_beta, dig_w2, dig_b2,
                                  aux_w2, aux_b2, out);
}

// round 10
// speedup vs baseline: 1.0757x; 1.0757x over previous
#include <cuda_runtime.h>
#include <cstdint>
#include <math.h>

// ---------------- problem constants ----------------
#define BT   16384          // B*T
#define D    1024
#define DQ   256
#define DH   512
#define NCAT 4096           // sign(512) + 6*512 + aux(512)
#define KDIM 1024
#define NSTAGE 32           // K / 32

// ---------------- scratch (device globals; no allocation allowed) ----------
__device__ float g_hid [(size_t)BT * D];        // tf32-rounded copy of hidden
__device__ float g_ctx [(size_t)BT * D];        // context (tf32-rounded after LN+GELU)
__device__ float g_H   [(size_t)BT * NCAT];     // head pre-activations
__device__ float g_Wctx[(size_t)KDIM * D];      // ctx_w[:1024,:], tf32-rounded   [K][N=1024]
__device__ float g_Wcat[(size_t)KDIM * NCAT];   // concat head W1, tf32-rounded   [K][N=4096]
__device__ float g_opc [9  * D];                // op contribution to ctx pre-LN
__device__ float g_ptc [10 * D];                // pt contribution (+ctx_b)
__device__ float g_hbias[NCAT];                 // per-column bias for H

// ---------------- helpers ----------------
__device__ __forceinline__ uint32_t f2tf32(float x) {
    uint32_t r;
    asm("cvt.rna.tf32.f32 %0, %1;" : "=r"(r) : "f"(x));
    return r;
}
__device__ __forceinline__ float rnd_tf32(float x) { return __uint_as_float(f2tf32(x)); }

__device__ __forceinline__ void mma_tf32(float* d, const uint32_t* a, uint32_t b0, uint32_t b1) {
    asm volatile(
        "mma.sync.aligned.m16n8k8.row.col.f32.tf32.tf32.f32 "
        "{%0,%1,%2,%3},{%4,%5,%6,%7},{%8,%9},{%0,%1,%2,%3};"
        : "+f"(d[0]), "+f"(d[1]), "+f"(d[2]), "+f"(d[3])
        : "r"(a[0]), "r"(a[1]), "r"(a[2]), "r"(a[3]), "r"(b0), "r"(b1));
}

__device__ __forceinline__ float gelu_exact(float x) {
    return 0.5f * x * (1.0f + erff(x * 0.70710678118654752440f));
}
__device__ __forceinline__ float warp_allreduce(float v) {
#pragma unroll
    for (int o = 16; o; o >>= 1) v += __shfl_xor_sync(0xffffffffu, v, o);
    return v;
}
__device__ __forceinline__ uint32_t smem_to_u32(const void* p) {
    uint32_t a;
    asm("{ .reg .u64 t; cvta.to.shared.u64 t, %1; cvt.u32.u64 %0, t; }" : "=r"(a) : "l"(p));
    return a;
}

#define CP_ASYNC16(dst, src) \
    asm volatile("cp.async.cg.shared.global [%0], [%1], 16;" :: "r"(dst), "l"(src) : "memory")
#define CP_COMMIT() asm volatile("cp.async.commit_group;" ::: "memory")
#define CP_WAIT1()  asm volatile("cp.async.wait_group 1;" ::: "memory")
#define CP_WAIT0()  asm volatile("cp.async.wait_group 0;" ::: "memory")

// ---------------- precompute kernels ----------------
__global__ void round_hidden(const float* __restrict__ h) {
    size_t i = ((size_t)blockIdx.x * 256 + threadIdx.x) * 4;
    float4 v = *(const float4*)(h + i);
    v.x = rnd_tf32(v.x); v.y = rnd_tf32(v.y); v.z = rnd_tf32(v.z); v.w = rnd_tf32(v.w);
    *(float4*)(g_hid + i) = v;
}

// tf32-rounded weights, [K][N] layout (coalesced GEMM loads)
__global__ void pre_w(const float* __restrict__ sign_w1,
                      const float* __restrict__ dig_w1,
                      const float* __restrict__ aux_w1,
                      const float* __restrict__ ctx_w) {
    int idx = blockIdx.x * blockDim.x + threadIdx.x;
    if (idx < KDIM * NCAT) {                       // g_Wcat[k][n]
        int k = idx >> 12;
        int n = idx & 4095;
        float v;
        if (n < 512) {
            v = sign_w1[k * 512 + n];
        } else if (n < 3584) {
            int p = (n - 512) >> 9;
            int h = (n - 512) & 511;
            v = dig_w1[((size_t)p * 1280 + k) * 512 + h];
        } else {
            v = aux_w1[k * 512 + (n - 3584)];
        }
        g_Wcat[idx] = rnd_tf32(v);
    } else {                                       // g_Wctx = rnd(ctx_w[:1024][:]) (same layout)
        int j = idx - KDIM * NCAT;
        g_Wctx[j] = rnd_tf32(ctx_w[j]);
    }
}

__global__ void pre_small(const float* __restrict__ op_embed,
                          const float* __restrict__ pt_embed,
                          const float* __restrict__ pos_embed,
                          const float* __restrict__ ctx_w,
                          const float* __restrict__ ctx_b,
                          const float* __restrict__ sign_b1,
                          const float* __restrict__ dig_w1,
                          const float* __restrict__ dig_b1,
                          const float* __restrict__ aux_b1) {
    int idx = blockIdx.x * blockDim.x + threadIdx.x;
    if (idx < 9 * D) {                         // op contributions
        int o = idx >> 10, j = idx & 1023;
        float s = 0.f;
        for (int q = 0; q < DQ; q++)
            s += op_embed[o * DQ + q] * ctx_w[(size_t)(1024 + q) * D + j];
        g_opc[idx] = s;
    } else if (idx < 9 * D + 10 * D) {         // pt contributions (+ctx_b)
        int i2 = idx - 9 * D;
        int pt = i2 >> 10, j = i2 & 1023;
        float s = ctx_b[j];
        for (int q = 0; q < DQ; q++)
            s += pt_embed[pt * DQ + q] * ctx_w[(size_t)(1280 + q) * D + j];
        g_ptc[i2] = s;
    } else if (idx < 9 * D + 10 * D + NCAT) {  // head bias
        int n = idx - 19 * D;
        float v;
        if (n < 512) {
            v = sign_b1[n];
        } else if (n < 3584) {
            int p = (n - 512) >> 9;
            int h = (n - 512) & 511;
            float s = dig_b1[p * 512 + h];
            for (int q = 0; q < DQ; q++)
                s += pos_embed[p * DQ + q] * dig_w1[((size_t)p * 1280 + 1024 + q) * 512 + h];
            v = s;
        } else {
            v = aux_b1[n - 3584];
        }
        g_hbias[n] = v;
    }
}

// ---------------- TF32 mma.sync GEMM with cp.async double buffering --------
// C[M=16384, N] = A[16384,1024] @ B[1024,N]; operands pre-rounded to tf32.
// block tile 128x128, K-step 32, 8 warps (4M x 2N), warp tile 32x64.
// smem (dynamic, floats):  A tile = 128*36 = 4608 floats, B tile = 32*136 = 4352 floats
//   buf0: A at 0,    B at 4608
//   buf1: A at 8960, B at 13568        (8960 + 4608 = 13568 — FIXED overlap bug)
//   total 17920 floats = 71680 bytes
#define A_TILE_F 4608
#define B_TILE_F 4352
#define BUF1_A   8960
#define BUF1_B   13568
#define GEMM_SMEM_BYTES 71680

__global__ __launch_bounds__(256, 2)
void gemm_tc(const float* __restrict__ A, const float* __restrict__ B,
             float* __restrict__ C, int N) {
    extern __shared__ float sm[];
    const int tid  = threadIdx.x;
    const int warp = tid >> 5, lane = tid & 31;
    const int wm = warp & 3, wn = warp >> 2;
    const int g = lane >> 2, tg = lane & 3;
    const int mBase = blockIdx.y * 128;
    const int nBase = blockIdx.x * 128;
    const int rA = tid >> 3, cA = (tid & 7) << 2;     // A loader: 8 threads/row
    const int rB = tid >> 5, cB4 = (tid & 31) << 2;   // B loader: 32 threads/row
    const uint32_t sbase = smem_to_u32(sm);

    float acc[2][8][4];
#pragma unroll
    for (int mi = 0; mi < 2; mi++)
#pragma unroll
        for (int ni = 0; ni < 8; ni++)
#pragma unroll
            for (int c = 0; c < 4; c++) acc[mi][ni][c] = 0.f;

    // prefetch stage 0 into buf 0
    {
        const float* sA = A + (size_t)(mBase + rA) * KDIM + cA;
        const float* sB = B + (size_t)rB * N + nBase + cB4;
#pragma unroll
        for (int j = 0; j < 4; j++) {
            CP_ASYNC16(sbase + 4u * ((rA + 32 * j) * 36 + cA), sA + (size_t)(32 * j) * KDIM);
            CP_ASYNC16(sbase + 4u * (4608 + (rB + 8 * j) * 136 + cB4), sB + (size_t)(8 * j) * N);
        }
        CP_COMMIT();
    }

    for (int kt = 0; kt < NSTAGE; kt++) {
        const int buf = kt & 1;
        if (kt + 1 < NSTAGE) {
            // prefetch next stage into the other buffer (freed by last iter's sync)
            const uint32_t ao = (buf ^ 1) ? (uint32_t)BUF1_A : 0u;
            const uint32_t bo = (buf ^ 1) ? (uint32_t)BUF1_B : 4608u;
            const float* sA = A + (size_t)(mBase + rA) * KDIM + (kt + 1) * 32 + cA;
            const float* sB = B + (size_t)((kt + 1) * 32 + rB) * N + nBase + cB4;
#pragma unroll
            for (int j = 0; j < 4; j++) {
                CP_ASYNC16(sbase + 4u * (ao + (rA + 32 * j) * 36 + cA), sA + (size_t)(32 * j) * KDIM);
                CP_ASYNC16(sbase + 4u * (bo + (rB + 8 * j) * 136 + cB4), sB + (size_t)(8 * j) * N);
            }
            CP_COMMIT();
            CP_WAIT1();             // stage kt has landed
        } else {
            CP_WAIT0();
        }
        __syncthreads();

        const float* As = sm + (buf ? BUF1_A : 0);
        const float* Bs = sm + (buf ? BUF1_B : 4608);
#pragma unroll
        for (int k8 = 0; k8 < 4; k8++) {
            const int kk = k8 * 8;
            uint32_t a[2][4];
#pragma unroll
            for (int mi = 0; mi < 2; mi++) {
                int r0 = wm * 32 + mi * 16;
                a[mi][0] = __float_as_uint(As[(r0 + g    ) * 36 + kk + tg    ]);
                a[mi][1] = __float_as_uint(As[(r0 + g + 8) * 36 + kk + tg    ]);
                a[mi][2] = __float_as_uint(As[(r0 + g    ) * 36 + kk + tg + 4]);
                a[mi][3] = __float_as_uint(As[(r0 + g + 8) * 36 + kk + tg + 4]);
            }
#pragma unroll
            for (int ni = 0; ni < 8; ni++) {
                int cB = wn * 64 + ni * 8 + g;
                uint32_t b0 = __float_as_uint(Bs[(kk + tg    ) * 136 + cB]);
                uint32_t b1 = __float_as_uint(Bs[(kk + tg + 4) * 136 + cB]);
#pragma unroll
                for (int mi = 0; mi < 2; mi++) mma_tf32(acc[mi][ni], a[mi], b0, b1);
            }
        }
        __syncthreads();            // buf free for prefetch at kt+2
    }

    // store
#pragma unroll
    for (int mi = 0; mi < 2; mi++) {
#pragma unroll
        for (int ni = 0; ni < 8; ni++) {
            int r0 = mBase + wm * 32 + mi * 16 + g;
            int c0 = nBase + wn * 64 + ni * 8 + tg * 2;
            *(float2*)(C + (size_t)r0 * N + c0)       = make_float2(acc[mi][ni][0], acc[mi][ni][1]);
            *(float2*)(C + (size_t)(r0 + 8) * N + c0) = make_float2(acc[mi][ni][2], acc[mi][ni][3]);
        }
    }
}

// ---------------- context: add contribs, LayerNorm(1024), GELU, tf32-round --
__global__ __launch_bounds__(256)
void ln_ctx(const int* __restrict__ op_type, const int* __restrict__ pt_type,
            const float* __restrict__ gam, const float* __restrict__ bet) {
    __shared__ float sred[8];
    const int t = blockIdx.x;
    const int b = t >> 11;
    const int op = op_type[b];
    const int pt = pt_type[t];
    const int tid = threadIdx.x;
    const int warp = tid >> 5, lane = tid & 31;

    float x[4];
#pragma unroll
    for (int i = 0; i < 4; i++) {
        int c = tid + 256 * i;
        x[i] = g_ctx[(size_t)t * D + c] + g_opc[op * D + c] + g_ptc[pt * D + c];
    }
    float s = x[0] + x[1] + x[2] + x[3];
    s = warp_allreduce(s);
    if (lane == 0) sred[warp] = s;
    __syncthreads();
    float m;
    {
        float v = (lane < 8) ? sred[lane] : 0.f;
        v = warp_allreduce(v);
        m = __shfl_sync(0xffffffffu, v, 0) * (1.0f / 1024.0f);
    }
    __syncthreads();
    float q = 0.f;
#pragma unroll
    for (int i = 0; i < 4; i++) { float d = x[i] - m; q += d * d; }
    q = warp_allreduce(q);
    if (lane == 0) sred[warp] = q;
    __syncthreads();
    float var;
    {
        float v = (lane < 8) ? sred[lane] : 0.f;
        v = warp_allreduce(v);
        var = __shfl_sync(0xffffffffu, v, 0) * (1.0f / 1024.0f);
    }
    float r = rsqrtf(var + 1e-5f);
#pragma unroll
    for (int i = 0; i < 4; i++) {
        int c = tid + 256 * i;
        float y = (x[i] - m) * r * gam[c] + bet[c];
        g_ctx[(size_t)t * D + c] = rnd_tf32(gelu_exact(y));   // pre-rounded GEMM2 operand
    }
}

// ---------------- head epilogue: 1 block/token, 1 warp/segment -------------
__global__ __launch_bounds__(256)
void heads_epilogue(const float* __restrict__ sign_g,  const float* __restrict__ sign_beta,
                    const float* __restrict__ sign_w2, const float* __restrict__ sign_b2,
                    const float* __restrict__ dig_g,   const float* __restrict__ dig_beta,
                    const float* __restrict__ dig_w2,  const float* __restrict__ dig_b2,
                    const float* __restrict__ aux_w2,  const float* __restrict__ aux_b2,
                    float* __restrict__ out) {
    const int t = blockIdx.x;
    const int warp = threadIdx.x >> 5, lane = threadIdx.x & 31;
    const int segBase = warp * 512;

    float x[16];
#pragma unroll
    for (int i = 0; i < 16; i++) {
        int h = lane + 32 * i;
        x[i] = g_H[(size_t)t * NCAT + segBase + h] + g_hbias[segBase + h];
    }

    float y[16];
    if (warp < 7) {
        float s = 0.f;
#pragma unroll
        for (int i = 0; i < 16; i++) s += x[i];
        s = warp_allreduce(s);
        float m = s * (1.0f / 512.0f);
        float q = 0.f;
#pragma unroll
        for (int i = 0; i < 16; i++) { float d = x[i] - m; q += d * d; }
        q = warp_allreduce(q);
        float r = rsqrtf(q * (1.0f / 512.0f) + 1e-5f);

        const float* gam;
        const float* bet;
        if (warp == 0) { gam = sign_g; bet = sign_beta; }
        else           { gam = dig_g + (warp - 1) * 512; bet = dig_beta + (warp - 1) * 512; }
#pragma unroll
        for (int i = 0; i < 16; i++) {
            int h = lane + 32 * i;
            y[i] = gelu_exact((x[i] - m) * r * gam[h] + bet[h]);
        }
    } else {
#pragma unroll
        for (int i = 0; i < 16; i++) y[i] = gelu_exact(x[i]);
    }

    const size_t S0 = (size_t)BT * 3;
    const size_t S1 = S0 + (size_t)BT * 60;
    int nout; const float* w2; const float* b2; float* obase;
    if (warp == 0)      { nout = 3;  w2 = sign_w2;                   b2 = sign_b2;         obase = out + (size_t)t * 3; }
    else if (warp < 7)  { int p = warp - 1;
                          nout = 10; w2 = dig_w2 + (size_t)p * 5120; b2 = dig_b2 + p * 10; obase = out + S0 + (size_t)t * 60 + p * 10; }
    else                { nout = 1;  w2 = aux_w2;                    b2 = aux_b2;          obase = out + S1 + t; }

    for (int o = 0; o < nout; o++) {
        float p = 0.f;
#pragma unroll
        for (int i = 0; i < 16; i++) p += y[i] * w2[(lane + 32 * i) * nout + o];
        p = warp_allreduce(p);
        if (lane == 0) obase[o] = p + b2[o];
    }
}

// ---------------- launch ----------------
extern "C" void kernel_launch(void* const* d_in, const int* in_sizes, int n_in,
                              void* d_out, int out_size) {
    const float* hidden    = (const float*)d_in[0];
    const int*   op_type   = (const int*)  d_in[1];
    const int*   pt_type   = (const int*)  d_in[2];
    const float* op_embed  = (const float*)d_in[3];
    const float* pt_embed  = (const float*)d_in[4];
    const float* pos_embed = (const float*)d_in[5];
    const float* ctx_w     = (const float*)d_in[6];
    const float* ctx_b     = (const float*)d_in[7];
    const float* ctx_g     = (const float*)d_in[8];
    const float* ctx_beta  = (const float*)d_in[9];
    const float* sign_w1   = (const float*)d_in[10];
    const float* sign_b1   = (const float*)d_in[11];
    const float* sign_g    = (const float*)d_in[12];
    const float* sign_beta = (const float*)d_in[13];
    const float* sign_w2   = (const float*)d_in[14];
    const float* sign_b2   = (const float*)d_in[15];
    const float* dig_w1    = (const float*)d_in[16];
    const float* dig_b1    = (const float*)d_in[17];
    const float* dig_g     = (const float*)d_in[18];
    const float* dig_beta  = (const float*)d_in[19];
    const float* dig_w2    = (const float*)d_in[20];
    const float* dig_b2    = (const float*)d_in[21];
    const float* aux_w1    = (const float*)d_in[22];
    const float* aux_b1    = (const float*)d_in[23];
    const float* aux_w2    = (const float*)d_in[24];
    const float* aux_b2    = (const float*)d_in[25];
    float* out = (float*)d_out;

    float *hid_ptr, *ctx_ptr, *H_ptr, *Wctx_ptr, *Wcat_ptr;
    cudaGetSymbolAddress((void**)&hid_ptr,  g_hid);
    cudaGetSymbolAddress((void**)&ctx_ptr,  g_ctx);
    cudaGetSymbolAddress((void**)&H_ptr,    g_H);
    cudaGetSymbolAddress((void**)&Wctx_ptr, g_Wctx);
    cudaGetSymbolAddress((void**)&Wcat_ptr, g_Wcat);

    cudaFuncSetAttribute(gemm_tc, cudaFuncAttributeMaxDynamicSharedMemorySize, GEMM_SMEM_BYTES);

    // 1. precompute (tf32-rounded operands + small tables)
    round_hidden<<< (BT * D) / 1024, 256 >>>(hidden);
    pre_w       <<< (KDIM * NCAT + KDIM * D) / 256, 256 >>>(sign_w1, dig_w1, aux_w1, ctx_w);
    pre_small   <<< (9 * D + 10 * D + NCAT + 255) / 256, 256 >>>
        (op_embed, pt_embed, pos_embed, ctx_w, ctx_b, sign_b1, dig_w1, dig_b1, aux_b1);

    // 2. context GEMM  [16384,1024] @ [1024,1024]
    gemm_tc<<< dim3(D / 128, BT / 128), 256, GEMM_SMEM_BYTES >>>(hid_ptr, Wctx_ptr, ctx_ptr, D);

    // 3. context LN + GELU (+ op/pt contributions), tf32-rounded output
    ln_ctx<<< BT, 256 >>>(op_type, pt_type, ctx_g, ctx_beta);

    // 4. fused head GEMM  [16384,1024] @ [1024,4096]
    gemm_tc<<< dim3(NCAT / 128, BT / 128), 256, GEMM_SMEM_BYTES >>>(ctx_ptr, Wcat_ptr, H_ptr, NCAT);

    // 5. head epilogue -> outputs (sign | digit | aux)
    heads_epilogue<<< BT, 256 >>>(sign_g, sign_beta, sign_w2, sign_b2,
                                  dig_g, dig_beta, dig_w2, dig_b2,
                                  aux_w2, aux_b2, out);
}

// round 14
// speedup vs baseline: 1.1368x; 1.0568x over previous
#include <cuda_runtime.h>
#include <cstdint>
#include <math.h>

// ---------------- problem constants ----------------
#define BT   16384          // B*T
#define D    1024
#define DQ   256
#define DH   512
#define NCAT 4096           // sign(512) + 6*512 + aux(512)
#define KDIM 1024
#define NSTAGE 32           // K / 32

// ---------------- scratch (device globals; no allocation allowed) ----------
__device__ float g_hid [(size_t)BT * D];        // tf32-rounded copy of hidden
__device__ float g_ctx [(size_t)BT * D];        // context (tf32-rounded after LN+GELU)
__device__ float g_H   [(size_t)BT * NCAT];     // head pre-activations
__device__ float g_Wctx[(size_t)KDIM * D];      // ctx_w[:1024,:], tf32-rounded   [K][N=1024]
__device__ float g_Wcat[(size_t)KDIM * NCAT];   // concat head W1, tf32-rounded   [K][N=4096]
__device__ float g_opc [9  * D];                // op contribution to ctx pre-LN
__device__ float g_ptc [10 * D];                // pt contribution (+ctx_b)
__device__ float g_hbias[NCAT];                 // per-column bias for H

// ---------------- helpers ----------------
__device__ __forceinline__ uint32_t f2tf32(float x) {
    uint32_t r;
    asm("cvt.rna.tf32.f32 %0, %1;" : "=r"(r) : "f"(x));
    return r;
}
__device__ __forceinline__ float rnd_tf32(float x) { return __uint_as_float(f2tf32(x)); }

__device__ __forceinline__ void mma_tf32(float* d, const uint32_t* a, uint32_t b0, uint32_t b1) {
    asm volatile(
        "mma.sync.aligned.m16n8k8.row.col.f32.tf32.tf32.f32 "
        "{%0,%1,%2,%3},{%4,%5,%6,%7},{%8,%9},{%0,%1,%2,%3};"
        : "+f"(d[0]), "+f"(d[1]), "+f"(d[2]), "+f"(d[3])
        : "r"(a[0]), "r"(a[1]), "r"(a[2]), "r"(a[3]), "r"(b0), "r"(b1));
}

__device__ __forceinline__ float gelu_exact(float x) {
    return 0.5f * x * (1.0f + erff(x * 0.70710678118654752440f));
}
__device__ __forceinline__ float warp_allreduce(float v) {
#pragma unroll
    for (int o = 16; o; o >>= 1) v += __shfl_xor_sync(0xffffffffu, v, o);
    return v;
}
__device__ __forceinline__ uint32_t smem_to_u32(const void* p) {
    uint32_t a;
    asm("{ .reg .u64 t; cvta.to.shared.u64 t, %1; cvt.u32.u64 %0, t; }" : "=r"(a) : "l"(p));
    return a;
}

#define CP_ASYNC16(dst, src) \
    asm volatile("cp.async.cg.shared.global [%0], [%1], 16;" :: "r"(dst), "l"(src) : "memory")
#define CP_COMMIT() asm volatile("cp.async.commit_group;" ::: "memory")
#define CP_WAIT1()  asm volatile("cp.async.wait_group 1;" ::: "memory")
#define CP_WAIT0()  asm volatile("cp.async.wait_group 0;" ::: "memory")

// ---------------- precompute kernels ----------------
__global__ void round_hidden(const float* __restrict__ h) {
    size_t i = ((size_t)blockIdx.x * 256 + threadIdx.x) * 4;
    float4 v = *(const float4*)(h + i);
    v.x = rnd_tf32(v.x); v.y = rnd_tf32(v.y); v.z = rnd_tf32(v.z); v.w = rnd_tf32(v.w);
    *(float4*)(g_hid + i) = v;
}

// tf32-rounded weights, [K][N] layout (coalesced GEMM loads)
__global__ void pre_w(const float* __restrict__ sign_w1,
                      const float* __restrict__ dig_w1,
                      const float* __restrict__ aux_w1,
                      const float* __restrict__ ctx_w) {
    int idx = blockIdx.x * blockDim.x + threadIdx.x;
    if (idx < KDIM * NCAT) {                       // g_Wcat[k][n]
        int k = idx >> 12;
        int n = idx & 4095;
        float v;
        if (n < 512) {
            v = sign_w1[k * 512 + n];
        } else if (n < 3584) {
            int p = (n - 512) >> 9;
            int h = (n - 512) & 511;
            v = dig_w1[((size_t)p * 1280 + k) * 512 + h];
        } else {
            v = aux_w1[k * 512 + (n - 3584)];
        }
        g_Wcat[idx] = rnd_tf32(v);
    } else {                                       // g_Wctx = rnd(ctx_w[:1024][:]) (same layout)
        int j = idx - KDIM * NCAT;
        g_Wctx[j] = rnd_tf32(ctx_w[j]);
    }
}

__global__ void pre_small(const float* __restrict__ op_embed,
                          const float* __restrict__ pt_embed,
                          const float* __restrict__ pos_embed,
                          const float* __restrict__ ctx_w,
                          const float* __restrict__ ctx_b,
                          const float* __restrict__ sign_b1,
                          const float* __restrict__ dig_w1,
                          const float* __restrict__ dig_b1,
                          const float* __restrict__ aux_b1) {
    int idx = blockIdx.x * blockDim.x + threadIdx.x;
    if (idx < 9 * D) {                         // op contributions
        int o = idx >> 10, j = idx & 1023;
        float s = 0.f;
        for (int q = 0; q < DQ; q++)
            s += op_embed[o * DQ + q] * ctx_w[(size_t)(1024 + q) * D + j];
        g_opc[idx] = s;
    } else if (idx < 9 * D + 10 * D) {         // pt contributions (+ctx_b)
        int i2 = idx - 9 * D;
        int pt = i2 >> 10, j = i2 & 1023;
        float s = ctx_b[j];
        for (int q = 0; q < DQ; q++)
            s += pt_embed[pt * DQ + q] * ctx_w[(size_t)(1280 + q) * D + j];
        g_ptc[i2] = s;
    } else if (idx < 9 * D + 10 * D + NCAT) {  // head bias
        int n = idx - 19 * D;
        float v;
        if (n < 512) {
            v = sign_b1[n];
        } else if (n < 3584) {
            int p = (n - 512) >> 9;
            int h = (n - 512) & 511;
            float s = dig_b1[p * 512 + h];
            for (int q = 0; q < DQ; q++)
                s += pos_embed[p * DQ + q] * dig_w1[((size_t)p * 1280 + 1024 + q) * 512 + h];
            v = s;
        } else {
            v = aux_b1[n - 3584];
        }
        g_hbias[n] = v;
    }
}

// ---------------- TF32 mma.sync GEMM with cp.async double buffering --------
// C[M=16384, N] = A[16384,1024] @ B[1024,N]; operands pre-rounded to tf32.
// block tile 128x128, K-step 32, 4 warps (2M x 2N), warp tile 64x64.
// smem (dynamic, floats):  A tile = 128*36 = 4608, B tile = 32*136 = 4352
//   buf0: A at 0,    B at 4608
//   buf1: A at 8960, B at 13568
//   total 17920 floats = 71680 bytes;  3 CTAs/SM (215KB smem, <=170 regs)
#define BUF1_A   8960
#define BUF1_B   13568
#define GEMM_SMEM_BYTES 71680

__global__ __launch_bounds__(128, 3)
void gemm_tc(const float* __restrict__ A, const float* __restrict__ B,
             float* __restrict__ C, int N) {
    extern __shared__ float sm[];
    const int tid  = threadIdx.x;
    const int warp = tid >> 5, lane = tid & 31;
    const int wm = warp & 1, wn = warp >> 1;          // 2M x 2N warps, 64x64 each
    const int g = lane >> 2, tg = lane & 3;
    const int mBase = blockIdx.y * 128;
    const int nBase = blockIdx.x * 128;
    const int rA = tid >> 3, cA = (tid & 7) << 2;     // A loader: 16 rows/pass, 8 passes
    const int rB = tid >> 5, cB4 = (tid & 31) << 2;   // B loader: 4 rows/pass, 8 passes
    const uint32_t sbase = smem_to_u32(sm);

    float acc[4][8][4];
#pragma unroll
    for (int mi = 0; mi < 4; mi++)
#pragma unroll
        for (int ni = 0; ni < 8; ni++)
#pragma unroll
            for (int c = 0; c < 4; c++) acc[mi][ni][c] = 0.f;

    // prefetch stage 0 into buf 0
    {
        const float* sA = A + (size_t)(mBase + rA) * KDIM + cA;
        const float* sB = B + (size_t)rB * N + nBase + cB4;
#pragma unroll
        for (int j = 0; j < 8; j++) {
            CP_ASYNC16(sbase + 4u * ((rA + 16 * j) * 36 + cA), sA + (size_t)(16 * j) * KDIM);
            CP_ASYNC16(sbase + 4u * (4608 + (rB + 4 * j) * 136 + cB4), sB + (size_t)(4 * j) * N);
        }
        CP_COMMIT();
    }

    for (int kt = 0; kt < NSTAGE; kt++) {
        const int buf = kt & 1;
        if (kt + 1 < NSTAGE) {
            // prefetch next stage into the other buffer (freed by last iter's sync)
            const uint32_t ao = (buf ^ 1) ? (uint32_t)BUF1_A : 0u;
            const uint32_t bo = (buf ^ 1) ? (uint32_t)BUF1_B : 4608u;
            const float* sA = A + (size_t)(mBase + rA) * KDIM + (kt + 1) * 32 + cA;
            const float* sB = B + (size_t)((kt + 1) * 32 + rB) * N + nBase + cB4;
#pragma unroll
            for (int j = 0; j < 8; j++) {
                CP_ASYNC16(sbase + 4u * (ao + (rA + 16 * j) * 36 + cA), sA + (size_t)(16 * j) * KDIM);
                CP_ASYNC16(sbase + 4u * (bo + (rB + 4 * j) * 136 + cB4), sB + (size_t)(4 * j) * N);
            }
            CP_COMMIT();
            CP_WAIT1();             // stage kt has landed
        } else {
            CP_WAIT0();
        }
        __syncthreads();

        const float* As = sm + (buf ? BUF1_A : 0);
        const float* Bs = sm + (buf ? BUF1_B : 4608);
#pragma unroll
        for (int k8 = 0; k8 < 4; k8++) {
            const int kk = k8 * 8;
            uint32_t a[4][4];
#pragma unroll
            for (int mi = 0; mi < 4; mi++) {
                int r0 = wm * 64 + mi * 16;
                a[mi][0] = __float_as_uint(As[(r0 + g    ) * 36 + kk + tg    ]);
                a[mi][1] = __float_as_uint(As[(r0 + g + 8) * 36 + kk + tg    ]);
                a[mi][2] = __float_as_uint(As[(r0 + g    ) * 36 + kk + tg + 4]);
                a[mi][3] = __float_as_uint(As[(r0 + g + 8) * 36 + kk + tg + 4]);
            }
#pragma unroll
            for (int ni = 0; ni < 8; ni++) {
                int cB = wn * 64 + ni * 8 + g;
                uint32_t b0 = __float_as_uint(Bs[(kk + tg    ) * 136 + cB]);
                uint32_t b1 = __float_as_uint(Bs[(kk + tg + 4) * 136 + cB]);
#pragma unroll
                for (int mi = 0; mi < 4; mi++) mma_tf32(acc[mi][ni], a[mi], b0, b1);
            }
        }
        __syncthreads();            // buf free for prefetch at kt+2
    }

    // store
#pragma unroll
    for (int mi = 0; mi < 4; mi++) {
#pragma unroll
        for (int ni = 0; ni < 8; ni++) {
            int r0 = mBase + wm * 64 + mi * 16 + g;
            int c0 = nBase + wn * 64 + ni * 8 + tg * 2;
            *(float2*)(C + (size_t)r0 * N + c0)       = make_float2(acc[mi][ni][0], acc[mi][ni][1]);
            *(float2*)(C + (size_t)(r0 + 8) * N + c0) = make_float2(acc[mi][ni][2], acc[mi][ni][3]);
        }
    }
}

// ---------------- context: add contribs, LayerNorm(1024), GELU, tf32-round --
__global__ __launch_bounds__(256)
void ln_ctx(const int* __restrict__ op_type, const int* __restrict__ pt_type,
            const float* __restrict__ gam, const float* __restrict__ bet) {
    __shared__ float sred[8];
    const int t = blockIdx.x;
    const int b = t >> 11;
    const int op = op_type[b];
    const int pt = pt_type[t];
    const int tid = threadIdx.x;
    const int warp = tid >> 5, lane = tid & 31;

    float x[4];
#pragma unroll
    for (int i = 0; i < 4; i++) {
        int c = tid + 256 * i;
        x[i] = g_ctx[(size_t)t * D + c] + g_opc[op * D + c] + g_ptc[pt * D + c];
    }
    float s = x[0] + x[1] + x[2] + x[3];
    s = warp_allreduce(s);
    if (lane == 0) sred[warp] = s;
    __syncthreads();
    float m;
    {
        float v = (lane < 8) ? sred[lane] : 0.f;
        v = warp_allreduce(v);
        m = __shfl_sync(0xffffffffu, v, 0) * (1.0f / 1024.0f);
    }
    __syncthreads();
    float q = 0.f;
#pragma unroll
    for (int i = 0; i < 4; i++) { float d = x[i] - m; q += d * d; }
    q = warp_allreduce(q);
    if (lane == 0) sred[warp] = q;
    __syncthreads();
    float var;
    {
        float v = (lane < 8) ? sred[lane] : 0.f;
        v = warp_allreduce(v);
        var = __shfl_sync(0xffffffffu, v, 0) * (1.0f / 1024.0f);
    }
    float r = rsqrtf(var + 1e-5f);
#pragma unroll
    for (int i = 0; i < 4; i++) {
        int c = tid + 256 * i;
        float y = (x[i] - m) * r * gam[c] + bet[c];
        g_ctx[(size_t)t * D + c] = rnd_tf32(gelu_exact(y));   // pre-rounded GEMM2 operand
    }
}

// ---------------- head epilogue: 1 block/token, 1 warp/segment -------------
__global__ __launch_bounds__(256)
void heads_epilogue(const float* __restrict__ sign_g,  const float* __restrict__ sign_beta,
                    const float* __restrict__ sign_w2, const float* __restrict__ sign_b2,
                    const float* __restrict__ dig_g,   const float* __restrict__ dig_beta,
                    const float* __restrict__ dig_w2,  const float* __restrict__ dig_b2,
                    const float* __restrict__ aux_w2,  const float* __restrict__ aux_b2,
                    float* __restrict__ out) {
    const int t = blockIdx.x;
    const int warp = threadIdx.x >> 5, lane = threadIdx.x & 31;
    const int segBase = warp * 512;

    float x[16];
#pragma unroll
    for (int i = 0; i < 16; i++) {
        int h = lane + 32 * i;
        x[i] = g_H[(size_t)t * NCAT + segBase + h] + g_hbias[segBase + h];
    }

    float y[16];
    if (warp < 7) {
        float s = 0.f;
#pragma unroll
        for (int i = 0; i < 16; i++) s += x[i];
        s = warp_allreduce(s);
        float m = s * (1.0f / 512.0f);
        float q = 0.f;
#pragma unroll
        for (int i = 0; i < 16; i++) { float d = x[i] - m; q += d * d; }
        q = warp_allreduce(q);
        float r = rsqrtf(q * (1.0f / 512.0f) + 1e-5f);

        const float* gam;
        const float* bet;
        if (warp == 0) { gam = sign_g; bet = sign_beta; }
        else           { gam = dig_g + (warp - 1) * 512; bet = dig_beta + (warp - 1) * 512; }
#pragma unroll
        for (int i = 0; i < 16; i++) {
            int h = lane + 32 * i;
            y[i] = gelu_exact((x[i] - m) * r * gam[h] + bet[h]);
        }
    } else {
#pragma unroll
        for (int i = 0; i < 16; i++) y[i] = gelu_exact(x[i]);
    }

    const size_t S0 = (size_t)BT * 3;
    const size_t S1 = S0 + (size_t)BT * 60;
    int nout; const float* w2; const float* b2; float* obase;
    if (warp == 0)      { nout = 3;  w2 = sign_w2;                   b2 = sign_b2;         obase = out + (size_t)t * 3; }
    else if (warp < 7)  { int p = warp - 1;
                          nout = 10; w2 = dig_w2 + (size_t)p * 5120; b2 = dig_b2 + p * 10; obase = out + S0 + (size_t)t * 60 + p * 10; }
    else                { nout = 1;  w2 = aux_w2;                    b2 = aux_b2;          obase = out + S1 + t; }

    for (int o = 0; o < nout; o++) {
        float p = 0.f;
#pragma unroll
        for (int i = 0; i < 16; i++) p += y[i] * w2[(lane + 32 * i) * nout + o];
        p = warp_allreduce(p);
        if (lane == 0) obase[o] = p + b2[o];
    }
}

// ---------------- launch ----------------
extern "C" void kernel_launch(void* const* d_in, const int* in_sizes, int n_in,
                              void* d_out, int out_size) {
    const float* hidden    = (const float*)d_in[0];
    const int*   op_type   = (const int*)  d_in[1];
    const int*   pt_type   = (const int*)  d_in[2];
    const float* op_embed  = (const float*)d_in[3];
    const float* pt_embed  = (const float*)d_in[4];
    const float* pos_embed = (const float*)d_in[5];
    const float* ctx_w     = (const float*)d_in[6];
    const float* ctx_b     = (const float*)d_in[7];
    const float* ctx_g     = (const float*)d_in[8];
    const float* ctx_beta  = (const float*)d_in[9];
    const float* sign_w1   = (const float*)d_in[10];
    const float* sign_b1   = (const float*)d_in[11];
    const float* sign_g    = (const float*)d_in[12];
    const float* sign_beta = (const float*)d_in[13];
    const float* sign_w2   = (const float*)d_in[14];
    const float* sign_b2   = (const float*)d_in[15];
    const float* dig_w1    = (const float*)d_in[16];
    const float* dig_b1    = (const float*)d_in[17];
    const float* dig_g     = (const float*)d_in[18];
    const float* dig_beta  = (const float*)d_in[19];
    const float* dig_w2    = (const float*)d_in[20];
    const float* dig_b2    = (const float*)d_in[21];
    const float* aux_w1    = (const float*)d_in[22];
    const float* aux_b1    = (const float*)d_in[23];
    const float* aux_w2    = (const float*)d_in[24];
    const float* aux_b2    = (const float*)d_in[25];
    float* out = (float*)d_out;

    float *hid_ptr, *ctx_ptr, *H_ptr, *Wctx_ptr, *Wcat_ptr;
    cudaGetSymbolAddress((void**)&hid_ptr,  g_hid);
    cudaGetSymbolAddress((void**)&ctx_ptr,  g_ctx);
    cudaGetSymbolAddress((void**)&H_ptr,    g_H);
    cudaGetSymbolAddress((void**)&Wctx_ptr, g_Wctx);
    cudaGetSymbolAddress((void**)&Wcat_ptr, g_Wcat);

    cudaFuncSetAttribute(gemm_tc, cudaFuncAttributeMaxDynamicSharedMemorySize, GEMM_SMEM_BYTES);

    // 1. precompute (tf32-rounded operands + small tables)
    round_hidden<<< (BT * D) / 1024, 256 >>>(hidden);
    pre_w       <<< (KDIM * NCAT + KDIM * D) / 256, 256 >>>(sign_w1, dig_w1, aux_w1, ctx_w);
    pre_small   <<< (9 * D + 10 * D + NCAT + 255) / 256, 256 >>>
        (op_embed, pt_embed, pos_embed, ctx_w, ctx_b, sign_b1, dig_w1, dig_b1, aux_b1);

    // 2. context GEMM  [16384,1024] @ [1024,1024]
    gemm_tc<<< dim3(D / 128, BT / 128), 128, GEMM_SMEM_BYTES >>>(hid_ptr, Wctx_ptr, ctx_ptr, D);

    // 3. context LN + GELU (+ op/pt contributions), tf32-rounded output
    ln_ctx<<< BT, 256 >>>(op_type, pt_type, ctx_g, ctx_beta);

    // 4. fused head GEMM  [16384,1024] @ [1024,4096]
    gemm_tc<<< dim3(NCAT / 128, BT / 128), 128, GEMM_SMEM_BYTES >>>(ctx_ptr, Wcat_ptr, H_ptr, NCAT);

    // 5. head epilogue -> outputs (sign | digit | aux)
    heads_epilogue<<< BT, 256 >>>(sign_g, sign_beta, sign_w2, sign_b2,
                                  dig_g, dig_beta, dig_w2, dig_b2,
                                  aux_w2, aux_b2, out);
}